// round 2
// baseline (speedup 1.0000x reference)
#include <cuda_runtime.h>
#include <math.h>

// Problem constants (fixed shapes from reference)
#define N_NODES 50000
#define N_EDGES 3200000
#define F_IN    8     // 4*NT
#define H1      64
#define H2      32
#define OUT5    5
#define N_ITERS 8

// ---------------- device scratch (no allocation allowed) ----------------
__device__ float g_x0[N_NODES * F_IN];
__device__ float g_x1[N_NODES * F_IN];
__device__ float g_aggr[N_NODES * H1];

// prepared (transposed / bias-folded / padded) weights
__device__ float g_W1[H1 * 16];     // [j][k]: k<13 -> w1_0[k][j], k==13 -> b1_0[j], else 0
__device__ float g_W2T[H1 * H1];    // [j][k] = w1_1[k][j]
__device__ float g_b11[H1];
__device__ float g_W3T[H2 * 80];    // [j][k]: k<72 -> w2_0[k][j], k==72 -> b2_0[j], else 0
__device__ float g_W4T[OUT5 * H2];  // [j][k] = w2_1[k][j]
__device__ float g_b21[OUT5];

// ---------------- weight preparation ----------------
__global__ void prep_kernel(const float* __restrict__ w10, const float* __restrict__ b10,
                            const float* __restrict__ w11, const float* __restrict__ b11,
                            const float* __restrict__ w20, const float* __restrict__ b20,
                            const float* __restrict__ w21, const float* __restrict__ b21) {
    int t = blockIdx.x * blockDim.x + threadIdx.x;
    if (t < H1 * 16) {
        int j = t >> 4, k = t & 15;
        float v = 0.f;
        if (k < 13)       v = w10[k * H1 + j];
        else if (k == 13) v = b10[j];
        g_W1[t] = v;
    }
    if (t < H1 * H1) {
        int j = t >> 6, k = t & 63;
        g_W2T[t] = w11[k * H1 + j];
    }
    if (t < H1) g_b11[t] = b11[t];
    if (t < H2 * 80) {
        int j = t / 80, k = t % 80;
        float v = 0.f;
        if (k < 72)       v = w20[k * H2 + j];
        else if (k == 72) v = b20[j];
        g_W3T[t] = v;
    }
    if (t < OUT5 * H2) {
        int j = t / H2, k = t % H2;
        g_W4T[t] = w21[k * OUT5 + j];
    }
    if (t < OUT5) g_b21[t] = b21[t];
}

// ---------------- zero the aggregation buffer ----------------
__global__ void zero_aggr_kernel() {
    int i = blockIdx.x * blockDim.x + threadIdx.x;
    const int n4 = (N_NODES * H1) / 4;
    if (i < n4) {
        float4 z = make_float4(0.f, 0.f, 0.f, 0.f);
        reinterpret_cast<float4*>(g_aggr)[i] = z;
    }
}

// ---------------- edge MLP + scatter-max ----------------
// thread-per-edge; h[64] in registers; weights in smem (broadcast reads);
// msg >= 0 after relu so atomicMax on int bit pattern is order-preserving.
__global__ __launch_bounds__(256, 2)
void edge_kernel(const float* __restrict__ x,
                 const float* __restrict__ eattr,
                 const int* __restrict__ eidx) {
    __shared__ float sW1[H1 * 16];
    __shared__ float sW2[H1 * H1];
    __shared__ float sb[H1];
    for (int i = threadIdx.x; i < H1 * 16; i += blockDim.x) sW1[i] = g_W1[i];
    for (int i = threadIdx.x; i < H1 * H1; i += blockDim.x) sW2[i] = g_W2T[i];
    if (threadIdx.x < H1) sb[threadIdx.x] = g_b11[threadIdx.x];
    __syncthreads();

    int stride = gridDim.x * blockDim.x;
    for (int e = blockIdx.x * blockDim.x + threadIdx.x; e < N_EDGES; e += stride) {
        int src = eidx[e];
        int dst = eidx[N_EDGES + e];

        float t[16];
        const float4* xr = reinterpret_cast<const float4*>(x + (long long)src * F_IN);
        float4 xa = __ldg(xr);
        float4 xb = __ldg(xr + 1);
        t[0] = xa.x; t[1] = xa.y; t[2] = xa.z; t[3] = xa.w;
        t[4] = xb.x; t[5] = xb.y; t[6] = xb.z; t[7] = xb.w;
        const float* ea = eattr + (long long)e * 5;
        t[8]  = __ldg(ea + 0);
        t[9]  = __ldg(ea + 1);
        t[10] = __ldg(ea + 2);
        t[11] = __ldg(ea + 3);
        t[12] = __ldg(ea + 4);
        t[13] = 1.f;  // bias slot
        t[14] = 0.f;
        t[15] = 0.f;

        // GEMM1: h[j] = relu( sum_k t[k] * W1[j][k] )   (bias folded in)
        float h[H1];
#pragma unroll
        for (int j = 0; j < H1; j++) {
            const float4* w = reinterpret_cast<const float4*>(sW1 + j * 16);
            float acc = 0.f;
#pragma unroll
            for (int q = 0; q < 4; q++) {
                float4 wv = w[q];
                acc += t[4 * q + 0] * wv.x;
                acc += t[4 * q + 1] * wv.y;
                acc += t[4 * q + 2] * wv.z;
                acc += t[4 * q + 3] * wv.w;
            }
            h[j] = fmaxf(acc, 0.f);
        }

        // GEMM2 + scatter: msg[j] = relu(b[j] + sum_k h[k]*W2T[j][k]); atomicMax into aggr
        int* ag = reinterpret_cast<int*>(g_aggr + (long long)dst * H1);
#pragma unroll 4
        for (int j = 0; j < H1; j++) {
            const float4* w = reinterpret_cast<const float4*>(sW2 + j * H1);
            float acc = sb[j];
#pragma unroll
            for (int q = 0; q < 16; q++) {
                float4 wv = w[q];
                acc += h[4 * q + 0] * wv.x;
                acc += h[4 * q + 1] * wv.y;
                acc += h[4 * q + 2] * wv.z;
                acc += h[4 * q + 3] * wv.w;
            }
            float m = fmaxf(acc, 0.f);
            atomicMax(ag + j, __float_as_int(m));  // m >= 0 -> int order == float order
        }
    }
}

// ---------------- node MLP + normalize + output assembly ----------------
__global__ void node_kernel(const float* __restrict__ x,
                            float* __restrict__ y) {
    __shared__ float sW3[H2 * 80];
    __shared__ float sW4[OUT5 * H2];
    __shared__ float sb2[OUT5];
    for (int i = threadIdx.x; i < H2 * 80; i += blockDim.x) sW3[i] = g_W3T[i];
    for (int i = threadIdx.x; i < OUT5 * H2; i += blockDim.x) sW4[i] = g_W4T[i];
    if (threadIdx.x < OUT5) sb2[threadIdx.x] = g_b21[threadIdx.x];
    __syncthreads();

    int n = blockIdx.x * blockDim.x + threadIdx.x;
    if (n >= N_NODES) return;

    float c[80];
    const float4* xr = reinterpret_cast<const float4*>(x + (long long)n * F_IN);
    float4 xa = xr[0];
    float4 xb = xr[1];
    c[0] = xa.x; c[1] = xa.y; c[2] = xa.z; c[3] = xa.w;
    c[4] = xb.x; c[5] = xb.y; c[6] = xb.z; c[7] = xb.w;
    const float4* ar = reinterpret_cast<const float4*>(g_aggr + (long long)n * H1);
#pragma unroll
    for (int q = 0; q < 16; q++) {
        float4 v = ar[q];
        c[8 + 4 * q + 0] = v.x;
        c[8 + 4 * q + 1] = v.y;
        c[8 + 4 * q + 2] = v.z;
        c[8 + 4 * q + 3] = v.w;
    }
    c[72] = 1.f;  // bias slot
#pragma unroll
    for (int k = 73; k < 80; k++) c[k] = 0.f;

    float h2[H2];
#pragma unroll
    for (int j = 0; j < H2; j++) {
        const float4* w = reinterpret_cast<const float4*>(sW3 + j * 80);
        float acc = 0.f;
#pragma unroll
        for (int q = 0; q < 20; q++) {
            float4 wv = w[q];
            acc += c[4 * q + 0] * wv.x;
            acc += c[4 * q + 1] * wv.y;
            acc += c[4 * q + 2] * wv.z;
            acc += c[4 * q + 3] * wv.w;
        }
        h2[j] = fmaxf(acc, 0.f);
    }

    float o[OUT5];
#pragma unroll
    for (int j = 0; j < OUT5; j++) {
        const float4* w = reinterpret_cast<const float4*>(sW4 + j * H2);
        float acc = sb2[j];
#pragma unroll
        for (int q = 0; q < 8; q++) {
            float4 wv = w[q];
            acc += h2[4 * q + 0] * wv.x;
            acc += h2[4 * q + 1] * wv.y;
            acc += h2[4 * q + 2] * wv.z;
            acc += h2[4 * q + 3] * wv.w;
        }
        o[j] = acc;
    }

    float nor = sqrtf(o[1] * o[1] + o[2] * o[2] + o[3] * o[3] + o[4] * o[4]);
    float d = fmaxf(1.f, nor);

    float* yr = y + (long long)n * F_IN;
    yr[0] = o[0];
    yr[1] = o[1] / d;
    yr[2] = o[2] / d;
    yr[3] = o[3] / d;
    yr[4] = o[4] / d;
    yr[5] = c[0];
    yr[6] = c[1];
    yr[7] = c[2];
}

// ---------------- host ----------------
extern "C" void kernel_launch(void* const* d_in, const int* in_sizes, int n_in,
                              void* d_out, int out_size) {
    const float* x_in = (const float*)d_in[0];
    const float* ea   = (const float*)d_in[1];
    const int*   ei   = (const int*)d_in[2];
    const float* w10  = (const float*)d_in[3];
    const float* b10  = (const float*)d_in[4];
    const float* w11  = (const float*)d_in[5];
    const float* b11  = (const float*)d_in[6];
    const float* w20  = (const float*)d_in[7];
    const float* b20  = (const float*)d_in[8];
    const float* w21  = (const float*)d_in[9];
    const float* b21  = (const float*)d_in[10];

    float* xb[2];
    cudaGetSymbolAddress((void**)&xb[0], g_x0);
    cudaGetSymbolAddress((void**)&xb[1], g_x1);

    prep_kernel<<<16, 256>>>(w10, b10, w11, b11, w20, b20, w21, b21);

    const int zero_threads = (N_NODES * H1) / 4;
    const int zero_blocks  = (zero_threads + 255) / 256;
    const int edge_blocks  = 296;  // persistent: 2 blocks/SM on 148 SMs
    const int node_blocks  = (N_NODES + 127) / 128;

    const float* xin = x_in;
    for (int it = 0; it < N_ITERS; it++) {
        zero_aggr_kernel<<<zero_blocks, 256>>>();
        edge_kernel<<<edge_blocks, 256>>>(xin, ea, ei);
        float* yout = (it == N_ITERS - 1) ? (float*)d_out : xb[it & 1];
        node_kernel<<<node_blocks, 128>>>(xin, yout);
        xin = yout;
    }
}